// round 8
// baseline (speedup 1.0000x reference)
#include <cuda_runtime.h>
#include <cstdint>

// Problem constants
#define BB   128   // batch
#define LL   196   // encoder length
#define EE   2048  // encoder dim
#define DD   1024  // decoder dim
#define AA   1024  // attention dim
#define USPLIT 4   // split-K of the u GEMM (fused kernel reduces these partials)

// ---------------- device scratch (no allocations allowed) ----------------
__device__ float g_decq[BB * AA];        // Wd @ h + bd           [128,1024]
__device__ float g_part[1 << 21];        // 8MB split-K partials (reused)
__device__ float g_fpart[2 * BB * EE];   // fused partial sums (unnormalized)
__device__ float g_fden[2 * BB];         // fused partial denominators

// ---------------- bf16 split helpers ----------------
__device__ __forceinline__ void pack2_bf(float x0, float x1,
                                         uint32_t& wh, uint32_t& wl) {
    asm("cvt.rn.bf16x2.f32 %0, %1, %2;" : "=r"(wh) : "f"(x1), "f"(x0));
    float h0 = __uint_as_float(wh << 16);
    float h1 = __uint_as_float(wh & 0xffff0000u);
    float l0 = x0 - h0;
    float l1 = x1 - h1;
    asm("cvt.rn.bf16x2.f32 %0, %1, %2;" : "=r"(wl) : "f"(l1), "f"(l0));
}

__device__ __forceinline__ void mma_bf16(float* c, const uint32_t* a,
                                         uint32_t b0, uint32_t b1) {
    asm volatile(
        "mma.sync.aligned.m16n8k16.row.col.f32.bf16.bf16.f32 "
        "{%0,%1,%2,%3}, {%4,%5,%6,%7}, {%8,%9}, {%0,%1,%2,%3};"
        : "+f"(c[0]), "+f"(c[1]), "+f"(c[2]), "+f"(c[3])
        : "r"(a[0]), "r"(a[1]), "r"(a[2]), "r"(a[3]), "r"(b0), "r"(b1));
}

// Smem: A planes [row][kpair] stride 20 (conflict-free frag reads),
// B packed fragment-major (see earlier layout notes).
struct SmemGemm {
    uint32_t Ah[2][128][20];
    uint32_t Al[2][128][20];
    uint32_t Bp[2][16 * 132];
};

// =====================================================================
// Tensor-core bf16x3 GEMM, split-K partials (unchanged core).
// =====================================================================
template <bool NN, int XSEL>
__global__ void __launch_bounds__(256, 2)
gemm_tc(const float* __restrict__ Xp, const float* __restrict__ W,
        int K, int N, int kchunk) {
    extern __shared__ SmemGemm sm_g[];
    SmemGemm* s = sm_g;

    const float* X = (XSEL == 1) ? (const float*)g_decq : Xp;

    const int t     = threadIdx.x;
    const int warp  = t >> 5;
    const int lane  = t & 31;
    const int group = lane >> 2;
    const int tg    = lane & 3;
    const int wm    = warp & 3;
    const int wn    = warp >> 2;
    const int n0    = blockIdx.x * 64;
    const int k0    = blockIdx.y * kchunk;

    float c[2][4][4];
#pragma unroll
    for (int mi = 0; mi < 2; mi++)
#pragma unroll
        for (int ni = 0; ni < 4; ni++)
#pragma unroll
            for (int r = 0; r < 4; r++) c[mi][ni][r] = 0.f;

    float4 ra[4];
    float4 rb[2];

    auto loadA = [&](int kt) {
#pragma unroll
        for (int j = 0; j < 4; j++) {
            const int idx = t + 256 * j;
            const int row = idx >> 3;
            const int kq  = idx & 7;
            if (XSEL == 2) {
                float4 p0 = *reinterpret_cast<const float4*>(
                    g_fpart + (size_t)row * EE + kt + kq * 4);
                float4 p1 = *reinterpret_cast<const float4*>(
                    g_fpart + (size_t)(BB + row) * EE + kt + kq * 4);
                ra[j] = make_float4(p0.x + p1.x, p0.y + p1.y, p0.z + p1.z, p0.w + p1.w);
            } else {
                ra[j] = *reinterpret_cast<const float4*>(X + (size_t)row * K + kt + kq * 4);
            }
        }
    };
    auto loadB = [&](int kt) {
        if (NN) {
            const int kp = t >> 4;
            const int nq = t & 15;
            rb[0] = *reinterpret_cast<const float4*>(W + (size_t)(kt + 2 * kp) * N + n0 + nq * 4);
            rb[1] = *reinterpret_cast<const float4*>(W + (size_t)(kt + 2 * kp + 1) * N + n0 + nq * 4);
        } else {
#pragma unroll
            for (int j = 0; j < 2; j++) {
                const int idx = t + 256 * j;
                const int n   = idx >> 3;
                const int kq  = idx & 7;
                rb[j] = *reinterpret_cast<const float4*>(W + (size_t)(n0 + n) * K + kt + kq * 4);
            }
        }
    };
    auto storeAB = [&](int bb) {
#pragma unroll
        for (int j = 0; j < 4; j++) {
            const int idx = t + 256 * j;
            const int row = idx >> 3;
            const int kq  = idx & 7;
            uint32_t wh0, wl0, wh1, wl1;
            pack2_bf(ra[j].x, ra[j].y, wh0, wl0);
            pack2_bf(ra[j].z, ra[j].w, wh1, wl1);
            *reinterpret_cast<uint2*>(&s->Ah[bb][row][2 * kq]) = make_uint2(wh0, wh1);
            *reinterpret_cast<uint2*>(&s->Al[bb][row][2 * kq]) = make_uint2(wl0, wl1);
        }
        uint32_t* bp = s->Bp[bb];
        if (NN) {
            const int kp   = t >> 4;
            const int nq   = t & 15;
            const int ks16 = kp >> 3;
            const int pp   = kp & 7;
            const int breg = (pp >= 4) ? 1 : 0;
            const int tgk  = pp & 3;
            const float e0[4] = {rb[0].x, rb[0].y, rb[0].z, rb[0].w};
            const float e1[4] = {rb[1].x, rb[1].y, rb[1].z, rb[1].w};
#pragma unroll
            for (int cc = 0; cc < 4; cc++) {
                const int n  = nq * 4 + cc;
                const int bi = (n >> 3) * 2 + ks16;
                uint32_t wh, wl;
                pack2_bf(e0[cc], e1[cc], wh, wl);
                uint32_t* base = bp + bi * 132 + ((n & 7) * 4 + tgk) * 4;
                base[breg]     = wh;
                base[breg + 2] = wl;
            }
        } else {
#pragma unroll
            for (int j = 0; j < 2; j++) {
                const int idx  = t + 256 * j;
                const int n    = idx >> 3;
                const int kq   = idx & 7;
                const int ks16 = kq >> 2;
                const int bi   = (n >> 3) * 2 + ks16;
                uint32_t* tb = bp + bi * 132 + ((n & 7) * 4) * 4;
                const float vals[4] = {rb[j].x, rb[j].y, rb[j].z, rb[j].w};
#pragma unroll
                for (int q = 0; q < 2; q++) {
                    const int pp   = (2 * kq + q) & 7;
                    const int breg = (pp >= 4) ? 1 : 0;
                    const int tgk  = pp & 3;
                    uint32_t wh, wl;
                    pack2_bf(vals[2 * q], vals[2 * q + 1], wh, wl);
                    uint32_t* base = tb + tgk * 4;
                    base[breg]     = wh;
                    base[breg + 2] = wl;
                }
            }
        }
    };
    auto compute = [&](int bb) {
        const uint32_t* bp = s->Bp[bb];
#pragma unroll
        for (int ks = 0; ks < 2; ks++) {
            const int base = ks * 8;
            uint32_t ah[2][4], al[2][4];
#pragma unroll
            for (int mi = 0; mi < 2; mi++) {
                const int rm = wm * 32 + mi * 16 + group;
                ah[mi][0] = s->Ah[bb][rm][base + tg];
                ah[mi][1] = s->Ah[bb][rm + 8][base + tg];
                ah[mi][2] = s->Ah[bb][rm][base + tg + 4];
                ah[mi][3] = s->Ah[bb][rm + 8][base + tg + 4];
                al[mi][0] = s->Al[bb][rm][base + tg];
                al[mi][1] = s->Al[bb][rm + 8][base + tg];
                al[mi][2] = s->Al[bb][rm][base + tg + 4];
                al[mi][3] = s->Al[bb][rm + 8][base + tg + 4];
            }
#pragma unroll
            for (int ni = 0; ni < 4; ni++) {
                const uint32_t* Bf = bp + ((wn * 4 + ni) * 2 + ks) * 132 + lane * 4;
                uint4 bv = *reinterpret_cast<const uint4*>(Bf);
#pragma unroll
                for (int mi = 0; mi < 2; mi++) {
                    mma_bf16(c[mi][ni], ah[mi], bv.x, bv.y);
                    mma_bf16(c[mi][ni], ah[mi], bv.z, bv.w);
                    mma_bf16(c[mi][ni], al[mi], bv.x, bv.y);
                }
            }
        }
    };

    loadA(k0);
    loadB(k0);
    storeAB(0);
    __syncthreads();

    const int nkb = kchunk >> 5;
    for (int kb = 0; kb < nkb; kb++) {
        const int cur = kb & 1;
        if (kb + 1 < nkb) {
            loadA(k0 + (kb + 1) * 32);
            loadB(k0 + (kb + 1) * 32);
        }
        compute(cur);
        if (kb + 1 < nkb) storeAB(cur ^ 1);
        __syncthreads();
    }

    float* pb = g_part + (size_t)blockIdx.y * (BB * N);
#pragma unroll
    for (int mi = 0; mi < 2; mi++) {
        const int row0 = wm * 32 + mi * 16 + group;
#pragma unroll
        for (int ni = 0; ni < 4; ni++) {
            const int col = n0 + wn * 32 + ni * 8 + 2 * tg;
            float2 v01 = {c[mi][ni][0], c[mi][ni][1]};
            float2 v23 = {c[mi][ni][2], c[mi][ni][3]};
            *reinterpret_cast<float2*>(pb + (size_t)row0 * N + col) = v01;
            *reinterpret_cast<float2*>(pb + (size_t)(row0 + 8) * N + col) = v23;
        }
    }
}

// =====================================================================
// Split-K reduce, compile-time S. OUTSEL: 0 -> out param, 1 -> g_decq
// =====================================================================
template <int OUTSEL, bool SCALE, int S>
__global__ void reduce_add_kernel(float* __restrict__ outp,
                                  const float* __restrict__ bias,
                                  int MN, int N) {
    float* out = (OUTSEL == 0) ? outp : (float*)g_decq;
    int i = (blockIdx.x * blockDim.x + threadIdx.x) * 4;
    if (i >= MN) return;
    float4 v[S];
#pragma unroll
    for (int k = 0; k < S; k++)
        v[k] = *reinterpret_cast<const float4*>(g_part + (size_t)k * MN + i);
    float4 sv = v[0];
#pragma unroll
    for (int k = 1; k < S; k++) {
        sv.x += v[k].x; sv.y += v[k].y; sv.z += v[k].z; sv.w += v[k].w;
    }
    if (SCALE) {
        const int m = i / N;
        const float inv = 1.f / (g_fden[m] + g_fden[BB + m]);
        sv.x *= inv; sv.y *= inv; sv.z *= inv; sv.w *= inv;
    }
    if (bias) {
        float4 bv = *reinterpret_cast<const float4*>(bias + (i % N));
        sv.x += bv.x; sv.y += bv.y; sv.z += bv.z; sv.w += bv.w;
    }
    *reinterpret_cast<float4*>(out + i) = sv;
}

// =====================================================================
// Fused attention pass. grid (BB, 2), 256 threads = 8 warps = 2 warp QUADS.
// Quarter-row per warp: each warp owns 1/4 row (x[4] float4 regs ~ 70 regs
// total -> 3 CTAs/SM -> 24 warps/SM). Quarter-dots combined via per-quad
// smem + named barrier (parity double-buffered), 2 rows in flight per CTA.
// - Stages u[b] by reducing the u-GEMM's USPLIT split-K partials.
// - Computes c[b] = bq . dec_q[b] inline.
// Writes UNNORMALIZED partial sums + partial denominators.
// =====================================================================
__global__ void __launch_bounds__(256, 3)
fused_attn_kernel(const float* __restrict__ enc, const float* __restrict__ bq) {
    const int b    = blockIdx.x;
    const int sp   = blockIdx.y;       // 0..1
    const int t    = threadIdx.x;      // 256
    const int warp = t >> 5;
    const int lane = t & 31;
    const int quad    = warp >> 2;     // 0..1
    const int quarter = warp & 3;      // 0..3 : which quarter of the row
    const int lstart = sp * 98;
    const int lend   = (lstart + 98 < LL) ? lstart + 98 : LL;

    extern __shared__ float smf[];
    float* u_s  = smf;                 // [2048]
    float* sacc = smf + EE;            // [2][2048] per-quad accumulators
    __shared__ float cred[8];
    __shared__ float dquad[2];
    __shared__ float pd[2][2][4];      // [quad][parity][quarter]
    __shared__ float c_sh;

    // ---- stage u[b] = sum of USPLIT u-GEMM partials
#pragma unroll
    for (int j = 0; j < 2; j++) {
        const int p = t + 256 * j;     // float4 index 0..511
        float4 a = *reinterpret_cast<const float4*>(g_part + (size_t)b * EE + 4 * p);
#pragma unroll
        for (int sK = 1; sK < USPLIT; sK++) {
            float4 v = *reinterpret_cast<const float4*>(
                g_part + (size_t)sK * (BB * EE) + (size_t)b * EE + 4 * p);
            a.x += v.x; a.y += v.y; a.z += v.z; a.w += v.w;
        }
        *reinterpret_cast<float4*>(u_s + 4 * p) = a;
    }

    // ---- c[b] = bq . dec_q[b] (fixed order)
    {
        const float* dq = g_decq + (size_t)b * AA;
        float cv = bq[t] * dq[t] + bq[t + 256] * dq[t + 256]
                 + bq[t + 512] * dq[t + 512] + bq[t + 768] * dq[t + 768];
#pragma unroll
        for (int o = 16; o > 0; o >>= 1) cv += __shfl_xor_sync(0xffffffffu, cv, o);
        if (lane == 0) cred[warp] = cv;
    }
    __syncthreads();
    if (t == 0) {
        float tot = 0.f;
        for (int i = 0; i < 8; i++) tot += cred[i];
        c_sh = tot;
    }
    __syncthreads();
    const float c_b = c_sh;

    // warp's quarter-row base (float4 units)
    const float4* encb4 = reinterpret_cast<const float4*>(enc + (size_t)b * LL * EE)
                        + quarter * 128;
    const float4* us4   = reinterpret_cast<const float4*>(u_s) + quarter * 128;

    float4 ma[4];
#pragma unroll
    for (int i = 0; i < 4; i++) ma[i] = make_float4(0.f, 0.f, 0.f, 0.f);
    float den = 0.f;

    const int barid = quad + 1;        // named barriers 1..2, 128 threads each

    // ---- main loop: one warp-quad per row, 2 rows in flight per CTA
    int parity = 0;
    for (int l = lstart + quad; l < lend; l += 2, parity ^= 1) {
        const float4* row = encb4 + (size_t)l * (EE / 4);
        float4 x[4];
#pragma unroll
        for (int i = 0; i < 4; i++) x[i] = row[lane + 32 * i];
        float d = 0.f;
#pragma unroll
        for (int i = 0; i < 4; i++) {
            float4 uu = us4[lane + 32 * i];
            d += x[i].x * uu.x + x[i].y * uu.y + x[i].z * uu.z + x[i].w * uu.w;
        }
#pragma unroll
        for (int o = 16; o > 0; o >>= 1) d += __shfl_xor_sync(0xffffffffu, d, o);
        if (lane == 0) pd[quad][parity][quarter] = d;
        asm volatile("bar.sync %0, 128;" :: "r"(barid) : "memory");
        const float z  = pd[quad][parity][0] + pd[quad][parity][1]
                       + pd[quad][parity][2] + pd[quad][parity][3] + c_b;
        const float th = 1.f - __fdividef(2.f, __expf(2.f * z) + 1.f);
        const float w  = __expf(th);
        if (quarter == 0) den += w;
#pragma unroll
        for (int i = 0; i < 4; i++) {
            ma[i].x += w * x[i].x; ma[i].y += w * x[i].y;
            ma[i].z += w * x[i].z; ma[i].w += w * x[i].w;
        }
    }

    // ---- per-quad store, then cross-quad combine (fixed order)
    float4* sw = reinterpret_cast<float4*>(sacc + (size_t)quad * EE) + quarter * 128;
#pragma unroll
    for (int i = 0; i < 4; i++) sw[lane + 32 * i] = ma[i];
    if (quarter == 0 && lane == 0) dquad[quad] = den;
    __syncthreads();

    float* pp = g_fpart + ((size_t)sp * BB + b) * EE;
#pragma unroll
    for (int j = 0; j < 2; j++) {
        const int p = t + 256 * j;     // float4 index 0..511
        float4 a = reinterpret_cast<const float4*>(sacc)[p];
        float4 v = reinterpret_cast<const float4*>(sacc + EE)[p];
        a.x += v.x; a.y += v.y; a.z += v.z; a.w += v.w;
        reinterpret_cast<float4*>(pp)[p] = a;
    }
    if (t == 0) g_fden[sp * BB + b] = dquad[0] + dquad[1];
}

// =====================================================================
// Launcher
// =====================================================================
extern "C" void kernel_launch(void* const* d_in, const int* in_sizes, int n_in,
                              void* d_out, int out_size) {
    const float* enc = (const float*)d_in[0];  // [128,196,2048]
    const float* dh  = (const float*)d_in[1];  // [128,1024]
    const float* Wq  = (const float*)d_in[2];  // [1024,2048]  (A,E)
    const float* bq  = (const float*)d_in[3];  // [1024]
    const float* Wv  = (const float*)d_in[4];  // [1024,2048]  (A,E)
    const float* bv  = (const float*)d_in[5];  // [1024]
    const float* Wd  = (const float*)d_in[6];  // [1024,1024]  (A,D)
    const float* bd  = (const float*)d_in[7];  // [1024]
    float* out = (float*)d_out;                // [128,1024]

    const int gsm = (int)sizeof(SmemGemm);     // ~57KB dynamic
    const int fsm = (EE + 2 * EE) * 4;         // 24KB dynamic
    cudaFuncSetAttribute(gemm_tc<false, 0>, cudaFuncAttributeMaxDynamicSharedMemorySize, gsm);
    cudaFuncSetAttribute(gemm_tc<true, 1>,  cudaFuncAttributeMaxDynamicSharedMemorySize, gsm);
    cudaFuncSetAttribute(gemm_tc<false, 2>, cudaFuncAttributeMaxDynamicSharedMemorySize, gsm);
    cudaFuncSetAttribute(fused_attn_kernel, cudaFuncAttributeMaxDynamicSharedMemorySize, fsm);

    // 1) dec_q = h @ Wd^T + bd   (NT, K=D=1024, split 16 -> 16x16 = 256 CTAs)
    gemm_tc<false, 0><<<dim3(AA / 64, 16), 256, gsm>>>(dh, Wd, DD, AA, DD / 16);
    reduce_add_kernel<1, false, 16><<<(BB * AA) / 1024, 256>>>(nullptr, bd, BB * AA, AA);

    // 2) u partials = dec_q @ Wq (NN, K=A=1024, split USPLIT -> 32x4 = 128 CTAs)
    gemm_tc<true, 1><<<dim3(EE / 64, USPLIT), 256, gsm>>>(nullptr, Wq, AA, EE, AA / USPLIT);

    // 3) fused: u-reduce + c + energies + weights + weighted encoder sum
    fused_attn_kernel<<<dim3(BB, 2), 256, fsm>>>(enc, bq);

    // 4) context = (P0+P1) @ Wv^T, then *1/sum(w) + bv in reduce epilogue
    //    (NT, K=E=2048, split 16 -> 16x16 = 256 CTAs)
    gemm_tc<false, 2><<<dim3(AA / 64, 16), 256, gsm>>>(nullptr, Wv, EE, AA, EE / 16);
    reduce_add_kernel<0, true, 16><<<(BB * AA) / 1024, 256>>>(out, bv, BB * AA, AA);
}

// round 9
// speedup vs baseline: 1.2170x; 1.2170x over previous
#include <cuda_runtime.h>
#include <cstdint>

// Problem constants
#define BB   128   // batch
#define LL   196   // encoder length
#define EE   2048  // encoder dim
#define DD   1024  // decoder dim
#define AA   1024  // attention dim
#define USPLIT 4   // split-K of the u GEMM (fused kernel reduces these partials)

// ---------------- device scratch (no allocations allowed) ----------------
__device__ float g_decq[BB * AA];        // Wd @ h + bd           [128,1024]
__device__ float g_part[1 << 21];        // 8MB split-K partials (reused)
__device__ float g_fpart[2 * BB * EE];   // fused partial sums (unnormalized)
__device__ float g_fden[2 * BB];         // fused partial denominators

// ---------------- bf16 split helpers ----------------
__device__ __forceinline__ void pack2_bf(float x0, float x1,
                                         uint32_t& wh, uint32_t& wl) {
    asm("cvt.rn.bf16x2.f32 %0, %1, %2;" : "=r"(wh) : "f"(x1), "f"(x0));
    float h0 = __uint_as_float(wh << 16);
    float h1 = __uint_as_float(wh & 0xffff0000u);
    float l0 = x0 - h0;
    float l1 = x1 - h1;
    asm("cvt.rn.bf16x2.f32 %0, %1, %2;" : "=r"(wl) : "f"(l1), "f"(l0));
}

__device__ __forceinline__ void mma_bf16(float* c, const uint32_t* a,
                                         uint32_t b0, uint32_t b1) {
    asm volatile(
        "mma.sync.aligned.m16n8k16.row.col.f32.bf16.bf16.f32 "
        "{%0,%1,%2,%3}, {%4,%5,%6,%7}, {%8,%9}, {%0,%1,%2,%3};"
        : "+f"(c[0]), "+f"(c[1]), "+f"(c[2]), "+f"(c[3])
        : "r"(a[0]), "r"(a[1]), "r"(a[2]), "r"(a[3]), "r"(b0), "r"(b1));
}

// Smem: A planes [row][kpair] stride 20 (conflict-free frag reads),
// B packed fragment-major (see earlier layout notes).
struct SmemGemm {
    uint32_t Ah[2][128][20];
    uint32_t Al[2][128][20];
    uint32_t Bp[2][16 * 132];
};

// =====================================================================
// Tensor-core bf16x3 GEMM, split-K partials (unchanged core).
// =====================================================================
template <bool NN, int XSEL>
__global__ void __launch_bounds__(256, 2)
gemm_tc(const float* __restrict__ Xp, const float* __restrict__ W,
        int K, int N, int kchunk) {
    extern __shared__ SmemGemm sm_g[];
    SmemGemm* s = sm_g;

    const float* X = (XSEL == 1) ? (const float*)g_decq : Xp;

    const int t     = threadIdx.x;
    const int warp  = t >> 5;
    const int lane  = t & 31;
    const int group = lane >> 2;
    const int tg    = lane & 3;
    const int wm    = warp & 3;
    const int wn    = warp >> 2;
    const int n0    = blockIdx.x * 64;
    const int k0    = blockIdx.y * kchunk;

    float c[2][4][4];
#pragma unroll
    for (int mi = 0; mi < 2; mi++)
#pragma unroll
        for (int ni = 0; ni < 4; ni++)
#pragma unroll
            for (int r = 0; r < 4; r++) c[mi][ni][r] = 0.f;

    float4 ra[4];
    float4 rb[2];

    auto loadA = [&](int kt) {
#pragma unroll
        for (int j = 0; j < 4; j++) {
            const int idx = t + 256 * j;
            const int row = idx >> 3;
            const int kq  = idx & 7;
            if (XSEL == 2) {
                float4 p0 = *reinterpret_cast<const float4*>(
                    g_fpart + (size_t)row * EE + kt + kq * 4);
                float4 p1 = *reinterpret_cast<const float4*>(
                    g_fpart + (size_t)(BB + row) * EE + kt + kq * 4);
                ra[j] = make_float4(p0.x + p1.x, p0.y + p1.y, p0.z + p1.z, p0.w + p1.w);
            } else {
                ra[j] = *reinterpret_cast<const float4*>(X + (size_t)row * K + kt + kq * 4);
            }
        }
    };
    auto loadB = [&](int kt) {
        if (NN) {
            const int kp = t >> 4;
            const int nq = t & 15;
            rb[0] = *reinterpret_cast<const float4*>(W + (size_t)(kt + 2 * kp) * N + n0 + nq * 4);
            rb[1] = *reinterpret_cast<const float4*>(W + (size_t)(kt + 2 * kp + 1) * N + n0 + nq * 4);
        } else {
#pragma unroll
            for (int j = 0; j < 2; j++) {
                const int idx = t + 256 * j;
                const int n   = idx >> 3;
                const int kq  = idx & 7;
                rb[j] = *reinterpret_cast<const float4*>(W + (size_t)(n0 + n) * K + kt + kq * 4);
            }
        }
    };
    auto storeAB = [&](int bb) {
#pragma unroll
        for (int j = 0; j < 4; j++) {
            const int idx = t + 256 * j;
            const int row = idx >> 3;
            const int kq  = idx & 7;
            uint32_t wh0, wl0, wh1, wl1;
            pack2_bf(ra[j].x, ra[j].y, wh0, wl0);
            pack2_bf(ra[j].z, ra[j].w, wh1, wl1);
            *reinterpret_cast<uint2*>(&s->Ah[bb][row][2 * kq]) = make_uint2(wh0, wh1);
            *reinterpret_cast<uint2*>(&s->Al[bb][row][2 * kq]) = make_uint2(wl0, wl1);
        }
        uint32_t* bp = s->Bp[bb];
        if (NN) {
            const int kp   = t >> 4;
            const int nq   = t & 15;
            const int ks16 = kp >> 3;
            const int pp   = kp & 7;
            const int breg = (pp >= 4) ? 1 : 0;
            const int tgk  = pp & 3;
            const float e0[4] = {rb[0].x, rb[0].y, rb[0].z, rb[0].w};
            const float e1[4] = {rb[1].x, rb[1].y, rb[1].z, rb[1].w};
#pragma unroll
            for (int cc = 0; cc < 4; cc++) {
                const int n  = nq * 4 + cc;
                const int bi = (n >> 3) * 2 + ks16;
                uint32_t wh, wl;
                pack2_bf(e0[cc], e1[cc], wh, wl);
                uint32_t* base = bp + bi * 132 + ((n & 7) * 4 + tgk) * 4;
                base[breg]     = wh;
                base[breg + 2] = wl;
            }
        } else {
#pragma unroll
            for (int j = 0; j < 2; j++) {
                const int idx  = t + 256 * j;
                const int n    = idx >> 3;
                const int kq   = idx & 7;
                const int ks16 = kq >> 2;
                const int bi   = (n >> 3) * 2 + ks16;
                uint32_t* tb = bp + bi * 132 + ((n & 7) * 4) * 4;
                const float vals[4] = {rb[j].x, rb[j].y, rb[j].z, rb[j].w};
#pragma unroll
                for (int q = 0; q < 2; q++) {
                    const int pp   = (2 * kq + q) & 7;
                    const int breg = (pp >= 4) ? 1 : 0;
                    const int tgk  = pp & 3;
                    uint32_t wh, wl;
                    pack2_bf(vals[2 * q], vals[2 * q + 1], wh, wl);
                    uint32_t* base = tb + tgk * 4;
                    base[breg]     = wh;
                    base[breg + 2] = wl;
                }
            }
        }
    };
    auto compute = [&](int bb) {
        const uint32_t* bp = s->Bp[bb];
#pragma unroll
        for (int ks = 0; ks < 2; ks++) {
            const int base = ks * 8;
            uint32_t ah[2][4], al[2][4];
#pragma unroll
            for (int mi = 0; mi < 2; mi++) {
                const int rm = wm * 32 + mi * 16 + group;
                ah[mi][0] = s->Ah[bb][rm][base + tg];
                ah[mi][1] = s->Ah[bb][rm + 8][base + tg];
                ah[mi][2] = s->Ah[bb][rm][base + tg + 4];
                ah[mi][3] = s->Ah[bb][rm + 8][base + tg + 4];
                al[mi][0] = s->Al[bb][rm][base + tg];
                al[mi][1] = s->Al[bb][rm + 8][base + tg];
                al[mi][2] = s->Al[bb][rm][base + tg + 4];
                al[mi][3] = s->Al[bb][rm + 8][base + tg + 4];
            }
#pragma unroll
            for (int ni = 0; ni < 4; ni++) {
                const uint32_t* Bf = bp + ((wn * 4 + ni) * 2 + ks) * 132 + lane * 4;
                uint4 bv = *reinterpret_cast<const uint4*>(Bf);
#pragma unroll
                for (int mi = 0; mi < 2; mi++) {
                    mma_bf16(c[mi][ni], ah[mi], bv.x, bv.y);
                    mma_bf16(c[mi][ni], ah[mi], bv.z, bv.w);
                    mma_bf16(c[mi][ni], al[mi], bv.x, bv.y);
                }
            }
        }
    };

    loadA(k0);
    loadB(k0);
    storeAB(0);
    __syncthreads();

    const int nkb = kchunk >> 5;
    for (int kb = 0; kb < nkb; kb++) {
        const int cur = kb & 1;
        if (kb + 1 < nkb) {
            loadA(k0 + (kb + 1) * 32);
            loadB(k0 + (kb + 1) * 32);
        }
        compute(cur);
        if (kb + 1 < nkb) storeAB(cur ^ 1);
        __syncthreads();
    }

    float* pb = g_part + (size_t)blockIdx.y * (BB * N);
#pragma unroll
    for (int mi = 0; mi < 2; mi++) {
        const int row0 = wm * 32 + mi * 16 + group;
#pragma unroll
        for (int ni = 0; ni < 4; ni++) {
            const int col = n0 + wn * 32 + ni * 8 + 2 * tg;
            float2 v01 = {c[mi][ni][0], c[mi][ni][1]};
            float2 v23 = {c[mi][ni][2], c[mi][ni][3]};
            *reinterpret_cast<float2*>(pb + (size_t)row0 * N + col) = v01;
            *reinterpret_cast<float2*>(pb + (size_t)(row0 + 8) * N + col) = v23;
        }
    }
}

// =====================================================================
// Split-K reduce, compile-time S. OUTSEL: 0 -> out param, 1 -> g_decq
// =====================================================================
template <int OUTSEL, bool SCALE, int S>
__global__ void reduce_add_kernel(float* __restrict__ outp,
                                  const float* __restrict__ bias,
                                  int MN, int N) {
    float* out = (OUTSEL == 0) ? outp : (float*)g_decq;
    int i = (blockIdx.x * blockDim.x + threadIdx.x) * 4;
    if (i >= MN) return;
    float4 v[S];
#pragma unroll
    for (int k = 0; k < S; k++)
        v[k] = *reinterpret_cast<const float4*>(g_part + (size_t)k * MN + i);
    float4 sv = v[0];
#pragma unroll
    for (int k = 1; k < S; k++) {
        sv.x += v[k].x; sv.y += v[k].y; sv.z += v[k].z; sv.w += v[k].w;
    }
    if (SCALE) {
        const int m = i / N;
        const float inv = 1.f / (g_fden[m] + g_fden[BB + m]);
        sv.x *= inv; sv.y *= inv; sv.z *= inv; sv.w *= inv;
    }
    if (bias) {
        float4 bv = *reinterpret_cast<const float4*>(bias + (i % N));
        sv.x += bv.x; sv.y += bv.y; sv.z += bv.z; sv.w += bv.w;
    }
    *reinterpret_cast<float4*>(out + i) = sv;
}

// =====================================================================
// Fused attention pass, cp.async pipelined. grid (BB, 2), 256 threads =
// 8 warps = 4 warp PAIRS. Chunks of 4 rows (32KB) double-buffered in smem
// via cp.async.cg; pair p computes row p of the chunk (half-row per warp,
// dots combined via per-pair smem + 64-thread named barrier).
// Load stream (LDGSTS) never blocks on compute -> DRAM stays saturated.
// - Stages u[b] by reducing the u-GEMM's USPLIT split-K partials.
// - Computes c[b] = bq . dec_q[b] inline.
// Writes UNNORMALIZED partial sums + partial denominators.
// =====================================================================
#define CHROWS 4
__global__ void __launch_bounds__(256, 2)
fused_attn_kernel(const float* __restrict__ enc, const float* __restrict__ bq) {
    const int b    = blockIdx.x;
    const int sp   = blockIdx.y;       // 0..1
    const int t    = threadIdx.x;      // 256
    const int warp = t >> 5;
    const int lane = t & 31;
    const int pair = warp >> 1;        // 0..3
    const int half = warp & 1;         // 0/1 : which half of the row
    const int lstart = sp * 98;
    const int lend   = lstart + 98;    // LL = 196 = 2*98 exactly

    extern __shared__ float smf[];
    float* u_s = smf;                            // [2048]  (8KB)
    float* buf = smf + EE;                       // [2][CHROWS*2048] (64KB)
    __shared__ float cred[8];
    __shared__ float dpair[4];
    __shared__ float pd[4][2][2];                // [pair][parity][half]
    __shared__ float c_sh;

    // ---- stage u[b] = sum of USPLIT u-GEMM partials
#pragma unroll
    for (int j = 0; j < 2; j++) {
        const int p = t + 256 * j;               // float4 index 0..511
        float4 a = *reinterpret_cast<const float4*>(g_part + (size_t)b * EE + 4 * p);
#pragma unroll
        for (int sK = 1; sK < USPLIT; sK++) {
            float4 v = *reinterpret_cast<const float4*>(
                g_part + (size_t)sK * (BB * EE) + (size_t)b * EE + 4 * p);
            a.x += v.x; a.y += v.y; a.z += v.z; a.w += v.w;
        }
        *reinterpret_cast<float4*>(u_s + 4 * p) = a;
    }

    // ---- c[b] = bq . dec_q[b] (fixed order)
    {
        const float* dq = g_decq + (size_t)b * AA;
        float cv = bq[t] * dq[t] + bq[t + 256] * dq[t + 256]
                 + bq[t + 512] * dq[t + 512] + bq[t + 768] * dq[t + 768];
#pragma unroll
        for (int o = 16; o > 0; o >>= 1) cv += __shfl_xor_sync(0xffffffffu, cv, o);
        if (lane == 0) cred[warp] = cv;
    }
    __syncthreads();
    if (t == 0) {
        float tot = 0.f;
        for (int i = 0; i < 8; i++) tot += cred[i];
        c_sh = tot;
    }
    __syncthreads();
    const float c_b = c_sh;

    const float* encb = enc + (size_t)b * LL * EE;
    const int nchunks = (98 + CHROWS - 1) / CHROWS;   // 25 (last chunk: 2 rows)

    // ---- cp.async fill of one chunk into buffer bb
    auto fill = [&](int bb, int ci) {
        const int c0 = lstart + ci * CHROWS;
        float* dst = buf + (size_t)bb * (CHROWS * EE);
#pragma unroll
        for (int j = 0; j < 8; j++) {
            const int idx = t + 256 * j;          // float4 idx 0..2047
            const int r   = idx >> 9;             // row in chunk
            const int v   = idx & 511;            // float4 within row
            const int l   = c0 + r;
            if (l < lend) {
                uint32_t saddr = (uint32_t)__cvta_generic_to_shared(dst + (size_t)idx * 4);
                const float* src = encb + (size_t)l * EE + v * 4;
                asm volatile("cp.async.cg.shared.global [%0], [%1], 16;\n"
                             :: "r"(saddr), "l"(src));
            }
        }
        asm volatile("cp.async.commit_group;\n");
    };

    float4 ma[8];
#pragma unroll
    for (int i = 0; i < 8; i++) ma[i] = make_float4(0.f, 0.f, 0.f, 0.f);
    float den = 0.f;

    const int barid = pair + 1;                   // named barriers 1..4
    const float4* us4 = reinterpret_cast<const float4*>(u_s) + half * 256;

    fill(0, 0);
    if (nchunks > 1) fill(1, 1);

    for (int ci = 0; ci < nchunks; ci++) {
        if (ci + 1 < nchunks)
            asm volatile("cp.async.wait_group 1;\n" ::: "memory");
        else
            asm volatile("cp.async.wait_group 0;\n" ::: "memory");
        __syncthreads();

        const int bb = ci & 1;
        const int parity = bb;
        const int l = lstart + ci * CHROWS + pair;
        if (l < lend) {
            const float4* row = reinterpret_cast<const float4*>(
                buf + (size_t)bb * (CHROWS * EE) + (size_t)pair * EE) + half * 256;
            float4 x[8];
#pragma unroll
            for (int i = 0; i < 8; i++) x[i] = row[lane + 32 * i];
            float d = 0.f;
#pragma unroll
            for (int i = 0; i < 8; i++) {
                float4 uu = us4[lane + 32 * i];
                d += x[i].x * uu.x + x[i].y * uu.y + x[i].z * uu.z + x[i].w * uu.w;
            }
#pragma unroll
            for (int o = 16; o > 0; o >>= 1) d += __shfl_xor_sync(0xffffffffu, d, o);
            if (lane == 0) pd[pair][parity][half] = d;
            asm volatile("bar.sync %0, 64;" :: "r"(barid) : "memory");
            const float z  = pd[pair][parity][0] + pd[pair][parity][1] + c_b;
            const float th = 1.f - __fdividef(2.f, __expf(2.f * z) + 1.f);
            const float w  = __expf(th);
            if (half == 0) den += w;
#pragma unroll
            for (int i = 0; i < 8; i++) {
                ma[i].x += w * x[i].x; ma[i].y += w * x[i].y;
                ma[i].z += w * x[i].z; ma[i].w += w * x[i].w;
            }
        }
        __syncthreads();
        if (ci + 2 < nchunks) fill(bb, ci + 2);
    }

    // ---- per-pair store into buf (reused as sacc), cross-pair combine
    float* sacc = buf;                            // [4][2048]
    float4* sw = reinterpret_cast<float4*>(sacc + (size_t)pair * EE) + half * 256;
#pragma unroll
    for (int i = 0; i < 8; i++) sw[lane + 32 * i] = ma[i];
    if (half == 0 && lane == 0) dpair[pair] = den;
    __syncthreads();

    float* pp = g_fpart + ((size_t)sp * BB + b) * EE;
#pragma unroll
    for (int j = 0; j < 2; j++) {
        const int p = t + 256 * j;                // float4 index 0..511
        float4 a = reinterpret_cast<const float4*>(sacc)[p];
#pragma unroll
        for (int q = 1; q < 4; q++) {
            float4 v = reinterpret_cast<const float4*>(sacc + (size_t)q * EE)[p];
            a.x += v.x; a.y += v.y; a.z += v.z; a.w += v.w;
        }
        reinterpret_cast<float4*>(pp)[p] = a;
    }
    if (t == 0) g_fden[sp * BB + b] = dpair[0] + dpair[1] + dpair[2] + dpair[3];
}

// =====================================================================
// Launcher
// =====================================================================
extern "C" void kernel_launch(void* const* d_in, const int* in_sizes, int n_in,
                              void* d_out, int out_size) {
    const float* enc = (const float*)d_in[0];  // [128,196,2048]
    const float* dh  = (const float*)d_in[1];  // [128,1024]
    const float* Wq  = (const float*)d_in[2];  // [1024,2048]  (A,E)
    const float* bq  = (const float*)d_in[3];  // [1024]
    const float* Wv  = (const float*)d_in[4];  // [1024,2048]  (A,E)
    const float* bv  = (const float*)d_in[5];  // [1024]
    const float* Wd  = (const float*)d_in[6];  // [1024,1024]  (A,D)
    const float* bd  = (const float*)d_in[7];  // [1024]
    float* out = (float*)d_out;                // [128,1024]

    const int gsm = (int)sizeof(SmemGemm);             // ~57KB dynamic
    const int fsm = (EE + 2 * CHROWS * EE) * 4;        // 8 + 64 = 72KB dynamic
    cudaFuncSetAttribute(gemm_tc<false, 0>, cudaFuncAttributeMaxDynamicSharedMemorySize, gsm);
    cudaFuncSetAttribute(gemm_tc<true, 1>,  cudaFuncAttributeMaxDynamicSharedMemorySize, gsm);
    cudaFuncSetAttribute(gemm_tc<false, 2>, cudaFuncAttributeMaxDynamicSharedMemorySize, gsm);
    cudaFuncSetAttribute(fused_attn_kernel, cudaFuncAttributeMaxDynamicSharedMemorySize, fsm);

    // 1) dec_q = h @ Wd^T + bd   (NT, K=D=1024, split 16 -> 16x16 = 256 CTAs)
    gemm_tc<false, 0><<<dim3(AA / 64, 16), 256, gsm>>>(dh, Wd, DD, AA, DD / 16);
    reduce_add_kernel<1, false, 16><<<(BB * AA) / 1024, 256>>>(nullptr, bd, BB * AA, AA);

    // 2) u partials = dec_q @ Wq (NN, K=A=1024, split USPLIT -> 32x4 = 128 CTAs)
    gemm_tc<true, 1><<<dim3(EE / 64, USPLIT), 256, gsm>>>(nullptr, Wq, AA, EE, AA / USPLIT);

    // 3) fused: u-reduce + c + energies + weights + weighted encoder sum
    fused_attn_kernel<<<dim3(BB, 2), 256, fsm>>>(enc, bq);

    // 4) context = (P0+P1) @ Wv^T, then *1/sum(w) + bv in reduce epilogue
    //    (NT, K=E=2048, split 16 -> 16x16 = 256 CTAs)
    gemm_tc<false, 2><<<dim3(AA / 64, 16), 256, gsm>>>(nullptr, Wv, EE, AA, EE / 16);
    reduce_add_kernel<0, true, 16><<<(BB * AA) / 1024, 256>>>(out, bv, BB * AA, AA);
}

// round 10
// speedup vs baseline: 1.2212x; 1.0034x over previous
#include <cuda_runtime.h>
#include <cstdint>

// Problem constants
#define BB   128   // batch
#define LL   196   // encoder length
#define EE   2048  // encoder dim
#define DD   1024  // decoder dim
#define AA   1024  // attention dim
#define USPLIT 4   // split-K of the u GEMM (fused kernel reduces these partials)
#define PDEPTH 3   // per-pair pipeline depth (row slots)

// ---------------- device scratch (no allocations allowed) ----------------
__device__ float g_decq[BB * AA];        // Wd @ h + bd           [128,1024]
__device__ float g_part[1 << 21];        // 8MB split-K partials (reused)
__device__ float g_fpart[2 * BB * EE];   // fused partial sums (unnormalized)
__device__ float g_fden[2 * BB];         // fused partial denominators

// ---------------- bf16 split helpers ----------------
__device__ __forceinline__ void pack2_bf(float x0, float x1,
                                         uint32_t& wh, uint32_t& wl) {
    asm("cvt.rn.bf16x2.f32 %0, %1, %2;" : "=r"(wh) : "f"(x1), "f"(x0));
    float h0 = __uint_as_float(wh << 16);
    float h1 = __uint_as_float(wh & 0xffff0000u);
    float l0 = x0 - h0;
    float l1 = x1 - h1;
    asm("cvt.rn.bf16x2.f32 %0, %1, %2;" : "=r"(wl) : "f"(l1), "f"(l0));
}

__device__ __forceinline__ void mma_bf16(float* c, const uint32_t* a,
                                         uint32_t b0, uint32_t b1) {
    asm volatile(
        "mma.sync.aligned.m16n8k16.row.col.f32.bf16.bf16.f32 "
        "{%0,%1,%2,%3}, {%4,%5,%6,%7}, {%8,%9}, {%0,%1,%2,%3};"
        : "+f"(c[0]), "+f"(c[1]), "+f"(c[2]), "+f"(c[3])
        : "r"(a[0]), "r"(a[1]), "r"(a[2]), "r"(a[3]), "r"(b0), "r"(b1));
}

// Smem: A planes [row][kpair] stride 20 (conflict-free frag reads),
// B packed fragment-major (see earlier layout notes).
struct SmemGemm {
    uint32_t Ah[2][128][20];
    uint32_t Al[2][128][20];
    uint32_t Bp[2][16 * 132];
};

// =====================================================================
// Tensor-core bf16x3 GEMM, split-K partials (unchanged core).
// =====================================================================
template <bool NN, int XSEL>
__global__ void __launch_bounds__(256, 2)
gemm_tc(const float* __restrict__ Xp, const float* __restrict__ W,
        int K, int N, int kchunk) {
    extern __shared__ SmemGemm sm_g[];
    SmemGemm* s = sm_g;

    const float* X = (XSEL == 1) ? (const float*)g_decq : Xp;

    const int t     = threadIdx.x;
    const int warp  = t >> 5;
    const int lane  = t & 31;
    const int group = lane >> 2;
    const int tg    = lane & 3;
    const int wm    = warp & 3;
    const int wn    = warp >> 2;
    const int n0    = blockIdx.x * 64;
    const int k0    = blockIdx.y * kchunk;

    float c[2][4][4];
#pragma unroll
    for (int mi = 0; mi < 2; mi++)
#pragma unroll
        for (int ni = 0; ni < 4; ni++)
#pragma unroll
            for (int r = 0; r < 4; r++) c[mi][ni][r] = 0.f;

    float4 ra[4];
    float4 rb[2];

    auto loadA = [&](int kt) {
#pragma unroll
        for (int j = 0; j < 4; j++) {
            const int idx = t + 256 * j;
            const int row = idx >> 3;
            const int kq  = idx & 7;
            if (XSEL == 2) {
                float4 p0 = *reinterpret_cast<const float4*>(
                    g_fpart + (size_t)row * EE + kt + kq * 4);
                float4 p1 = *reinterpret_cast<const float4*>(
                    g_fpart + (size_t)(BB + row) * EE + kt + kq * 4);
                ra[j] = make_float4(p0.x + p1.x, p0.y + p1.y, p0.z + p1.z, p0.w + p1.w);
            } else {
                ra[j] = *reinterpret_cast<const float4*>(X + (size_t)row * K + kt + kq * 4);
            }
        }
    };
    auto loadB = [&](int kt) {
        if (NN) {
            const int kp = t >> 4;
            const int nq = t & 15;
            rb[0] = *reinterpret_cast<const float4*>(W + (size_t)(kt + 2 * kp) * N + n0 + nq * 4);
            rb[1] = *reinterpret_cast<const float4*>(W + (size_t)(kt + 2 * kp + 1) * N + n0 + nq * 4);
        } else {
#pragma unroll
            for (int j = 0; j < 2; j++) {
                const int idx = t + 256 * j;
                const int n   = idx >> 3;
                const int kq  = idx & 7;
                rb[j] = *reinterpret_cast<const float4*>(W + (size_t)(n0 + n) * K + kt + kq * 4);
            }
        }
    };
    auto storeAB = [&](int bb) {
#pragma unroll
        for (int j = 0; j < 4; j++) {
            const int idx = t + 256 * j;
            const int row = idx >> 3;
            const int kq  = idx & 7;
            uint32_t wh0, wl0, wh1, wl1;
            pack2_bf(ra[j].x, ra[j].y, wh0, wl0);
            pack2_bf(ra[j].z, ra[j].w, wh1, wl1);
            *reinterpret_cast<uint2*>(&s->Ah[bb][row][2 * kq]) = make_uint2(wh0, wh1);
            *reinterpret_cast<uint2*>(&s->Al[bb][row][2 * kq]) = make_uint2(wl0, wl1);
        }
        uint32_t* bp = s->Bp[bb];
        if (NN) {
            const int kp   = t >> 4;
            const int nq   = t & 15;
            const int ks16 = kp >> 3;
            const int pp   = kp & 7;
            const int breg = (pp >= 4) ? 1 : 0;
            const int tgk  = pp & 3;
            const float e0[4] = {rb[0].x, rb[0].y, rb[0].z, rb[0].w};
            const float e1[4] = {rb[1].x, rb[1].y, rb[1].z, rb[1].w};
#pragma unroll
            for (int cc = 0; cc < 4; cc++) {
                const int n  = nq * 4 + cc;
                const int bi = (n >> 3) * 2 + ks16;
                uint32_t wh, wl;
                pack2_bf(e0[cc], e1[cc], wh, wl);
                uint32_t* base = bp + bi * 132 + ((n & 7) * 4 + tgk) * 4;
                base[breg]     = wh;
                base[breg + 2] = wl;
            }
        } else {
#pragma unroll
            for (int j = 0; j < 2; j++) {
                const int idx  = t + 256 * j;
                const int n    = idx >> 3;
                const int kq   = idx & 7;
                const int ks16 = kq >> 2;
                const int bi   = (n >> 3) * 2 + ks16;
                uint32_t* tb = bp + bi * 132 + ((n & 7) * 4) * 4;
                const float vals[4] = {rb[j].x, rb[j].y, rb[j].z, rb[j].w};
#pragma unroll
                for (int q = 0; q < 2; q++) {
                    const int pp   = (2 * kq + q) & 7;
                    const int breg = (pp >= 4) ? 1 : 0;
                    const int tgk  = pp & 3;
                    uint32_t wh, wl;
                    pack2_bf(vals[2 * q], vals[2 * q + 1], wh, wl);
                    uint32_t* base = tb + tgk * 4;
                    base[breg]     = wh;
                    base[breg + 2] = wl;
                }
            }
        }
    };
    auto compute = [&](int bb) {
        const uint32_t* bp = s->Bp[bb];
#pragma unroll
        for (int ks = 0; ks < 2; ks++) {
            const int base = ks * 8;
            uint32_t ah[2][4], al[2][4];
#pragma unroll
            for (int mi = 0; mi < 2; mi++) {
                const int rm = wm * 32 + mi * 16 + group;
                ah[mi][0] = s->Ah[bb][rm][base + tg];
                ah[mi][1] = s->Ah[bb][rm + 8][base + tg];
                ah[mi][2] = s->Ah[bb][rm][base + tg + 4];
                ah[mi][3] = s->Ah[bb][rm + 8][base + tg + 4];
                al[mi][0] = s->Al[bb][rm][base + tg];
                al[mi][1] = s->Al[bb][rm + 8][base + tg];
                al[mi][2] = s->Al[bb][rm][base + tg + 4];
                al[mi][3] = s->Al[bb][rm + 8][base + tg + 4];
            }
#pragma unroll
            for (int ni = 0; ni < 4; ni++) {
                const uint32_t* Bf = bp + ((wn * 4 + ni) * 2 + ks) * 132 + lane * 4;
                uint4 bv = *reinterpret_cast<const uint4*>(Bf);
#pragma unroll
                for (int mi = 0; mi < 2; mi++) {
                    mma_bf16(c[mi][ni], ah[mi], bv.x, bv.y);
                    mma_bf16(c[mi][ni], ah[mi], bv.z, bv.w);
                    mma_bf16(c[mi][ni], al[mi], bv.x, bv.y);
                }
            }
        }
    };

    loadA(k0);
    loadB(k0);
    storeAB(0);
    __syncthreads();

    const int nkb = kchunk >> 5;
    for (int kb = 0; kb < nkb; kb++) {
        const int cur = kb & 1;
        if (kb + 1 < nkb) {
            loadA(k0 + (kb + 1) * 32);
            loadB(k0 + (kb + 1) * 32);
        }
        compute(cur);
        if (kb + 1 < nkb) storeAB(cur ^ 1);
        __syncthreads();
    }

    float* pb = g_part + (size_t)blockIdx.y * (BB * N);
#pragma unroll
    for (int mi = 0; mi < 2; mi++) {
        const int row0 = wm * 32 + mi * 16 + group;
#pragma unroll
        for (int ni = 0; ni < 4; ni++) {
            const int col = n0 + wn * 32 + ni * 8 + 2 * tg;
            float2 v01 = {c[mi][ni][0], c[mi][ni][1]};
            float2 v23 = {c[mi][ni][2], c[mi][ni][3]};
            *reinterpret_cast<float2*>(pb + (size_t)row0 * N + col) = v01;
            *reinterpret_cast<float2*>(pb + (size_t)(row0 + 8) * N + col) = v23;
        }
    }
}

// =====================================================================
// Split-K reduce, compile-time S. OUTSEL: 0 -> out param, 1 -> g_decq
// =====================================================================
template <int OUTSEL, bool SCALE, int S>
__global__ void reduce_add_kernel(float* __restrict__ outp,
                                  const float* __restrict__ bias,
                                  int MN, int N) {
    float* out = (OUTSEL == 0) ? outp : (float*)g_decq;
    int i = (blockIdx.x * blockDim.x + threadIdx.x) * 4;
    if (i >= MN) return;
    float4 v[S];
#pragma unroll
    for (int k = 0; k < S; k++)
        v[k] = *reinterpret_cast<const float4*>(g_part + (size_t)k * MN + i);
    float4 sv = v[0];
#pragma unroll
    for (int k = 1; k < S; k++) {
        sv.x += v[k].x; sv.y += v[k].y; sv.z += v[k].z; sv.w += v[k].w;
    }
    if (SCALE) {
        const int m = i / N;
        const float inv = 1.f / (g_fden[m] + g_fden[BB + m]);
        sv.x *= inv; sv.y *= inv; sv.z *= inv; sv.w *= inv;
    }
    if (bias) {
        float4 bv = *reinterpret_cast<const float4*>(bias + (i % N));
        sv.x += bv.x; sv.y += bv.y; sv.z += bv.z; sv.w += bv.w;
    }
    *reinterpret_cast<float4*>(out + i) = sv;
}

// =====================================================================
// Fused attention pass, per-pair decoupled cp.async pipelines.
// grid (BB, 2), 256 threads = 8 warps = 4 warp PAIRS.
// Pair p owns rows l = lstart + p + 4*i. Each pair has PDEPTH private
// 8KB row slots. SELF-TARGETED cp.async: every thread loads exactly the
// 8 float4 it later reads -> slot reuse and visibility need NO barrier
// (own-thread wait_group + same-address ordering). The only per-row sync
// is one 64-thread named barrier for the 2-half dot exchange.
// - Stages u[b] by reducing the u-GEMM's USPLIT split-K partials.
// - Computes c[b] = bq . dec_q[b] inline.
// Writes UNNORMALIZED partial sums + partial denominators.
// =====================================================================
__global__ void __launch_bounds__(256, 2)
fused_attn_kernel(const float* __restrict__ enc, const float* __restrict__ bq) {
    const int b    = blockIdx.x;
    const int sp   = blockIdx.y;       // 0..1
    const int t    = threadIdx.x;      // 256
    const int warp = t >> 5;
    const int lane = t & 31;
    const int pair = warp >> 1;        // 0..3
    const int half = warp & 1;         // 0/1 : which half of the row
    const int lstart = sp * 98;
    const int nrows  = (98 - pair + 3) >> 2;   // pairs 0,1: 25; pairs 2,3: 24

    extern __shared__ float smf[];
    float* u_s = smf;                            // [2048]  (8KB)
    float* buf = smf + EE;                       // [4][PDEPTH][2048] (96KB)
    __shared__ float cred[8];
    __shared__ float dpair[4];
    __shared__ float pd[4][2][2];                // [pair][parity][half]
    __shared__ float c_sh;

    // ---- stage u[b] = sum of USPLIT u-GEMM partials
#pragma unroll
    for (int j = 0; j < 2; j++) {
        const int p = t + 256 * j;               // float4 index 0..511
        float4 a = *reinterpret_cast<const float4*>(g_part + (size_t)b * EE + 4 * p);
#pragma unroll
        for (int sK = 1; sK < USPLIT; sK++) {
            float4 v = *reinterpret_cast<const float4*>(
                g_part + (size_t)sK * (BB * EE) + (size_t)b * EE + 4 * p);
            a.x += v.x; a.y += v.y; a.z += v.z; a.w += v.w;
        }
        *reinterpret_cast<float4*>(u_s + 4 * p) = a;
    }

    // ---- c[b] = bq . dec_q[b] (fixed order)
    {
        const float* dq = g_decq + (size_t)b * AA;
        float cv = bq[t] * dq[t] + bq[t + 256] * dq[t + 256]
                 + bq[t + 512] * dq[t + 512] + bq[t + 768] * dq[t + 768];
#pragma unroll
        for (int o = 16; o > 0; o >>= 1) cv += __shfl_xor_sync(0xffffffffu, cv, o);
        if (lane == 0) cred[warp] = cv;
    }
    __syncthreads();
    if (t == 0) {
        float tot = 0.f;
        for (int i = 0; i < 8; i++) tot += cred[i];
        c_sh = tot;
    }
    __syncthreads();
    const float c_b = c_sh;

    const float* encb = enc + (size_t)b * LL * EE;
    float* mybuf = buf + (size_t)(pair * PDEPTH) * EE;     // this pair's slots
    const int fo = half * 256 + lane;                       // float4 offset base

    // self-targeted fill of row i into slot i%PDEPTH (one group per call)
    auto fill = [&](int i) {
        if (i < nrows) {
            const int l = lstart + pair + 4 * i;
            const float4* src = reinterpret_cast<const float4*>(encb + (size_t)l * EE) + fo;
            uint32_t sa = (uint32_t)__cvta_generic_to_shared(mybuf + (size_t)(i % PDEPTH) * EE)
                        + (uint32_t)fo * 16u;
#pragma unroll
            for (int q = 0; q < 8; q++) {
                asm volatile("cp.async.cg.shared.global [%0], [%1], 16;\n"
                             :: "r"(sa + q * 512u), "l"(src + q * 32));
            }
        }
        asm volatile("cp.async.commit_group;\n");
    };

    float4 ma[8];
#pragma unroll
    for (int i = 0; i < 8; i++) ma[i] = make_float4(0.f, 0.f, 0.f, 0.f);
    float den = 0.f;

    const float4* us4 = reinterpret_cast<const float4*>(u_s) + half * 256;
    const int barid = pair + 1;                   // named barriers 1..4, 64 thr

    fill(0); fill(1); fill(2);

    for (int i = 0; i < nrows; i++) {
        asm volatile("cp.async.wait_group %0;\n" :: "n"(PDEPTH - 1) : "memory");
        const float4* slot = reinterpret_cast<const float4*>(
            mybuf + (size_t)(i % PDEPTH) * EE) + fo;
        float4 x[8];
#pragma unroll
        for (int q = 0; q < 8; q++) x[q] = slot[q * 32];
        float d = 0.f;
#pragma unroll
        for (int q = 0; q < 8; q++) {
            float4 uu = us4[lane + 32 * q];
            d += x[q].x * uu.x + x[q].y * uu.y + x[q].z * uu.z + x[q].w * uu.w;
        }
#pragma unroll
        for (int o = 16; o > 0; o >>= 1) d += __shfl_xor_sync(0xffffffffu, d, o);
        const int par = i & 1;
        if (lane == 0) pd[pair][par][half] = d;
        asm volatile("bar.sync %0, 64;" :: "r"(barid) : "memory");
        const float z  = pd[pair][par][0] + pd[pair][par][1] + c_b;
        const float th = 1.f - __fdividef(2.f, __expf(2.f * z) + 1.f);
        const float w  = __expf(th);
        if (half == 0) den += w;
#pragma unroll
        for (int q = 0; q < 8; q++) {
            ma[q].x += w * x[q].x; ma[q].y += w * x[q].y;
            ma[q].z += w * x[q].z; ma[q].w += w * x[q].w;
        }
        fill(i + PDEPTH);
    }

    // drain remaining (empty) groups, then reuse buf as sacc
    asm volatile("cp.async.wait_group 0;\n" ::: "memory");
    __syncthreads();

    float* sacc = buf;                            // [4][2048]
    float4* sw = reinterpret_cast<float4*>(sacc + (size_t)pair * EE) + fo;
#pragma unroll
    for (int q = 0; q < 8; q++) sw[q * 32] = ma[q];
    if (half == 0 && lane == 0) dpair[pair] = den;
    __syncthreads();

    float* pp = g_fpart + ((size_t)sp * BB + b) * EE;
#pragma unroll
    for (int j = 0; j < 2; j++) {
        const int p = t + 256 * j;                // float4 index 0..511
        float4 a = reinterpret_cast<const float4*>(sacc)[p];
#pragma unroll
        for (int q = 1; q < 4; q++) {
            float4 v = reinterpret_cast<const float4*>(sacc + (size_t)q * EE)[p];
            a.x += v.x; a.y += v.y; a.z += v.z; a.w += v.w;
        }
        reinterpret_cast<float4*>(pp)[p] = a;
    }
    if (t == 0) g_fden[sp * BB + b] = dpair[0] + dpair[1] + dpair[2] + dpair[3];
}

// =====================================================================
// Launcher
// =====================================================================
extern "C" void kernel_launch(void* const* d_in, const int* in_sizes, int n_in,
                              void* d_out, int out_size) {
    const float* enc = (const float*)d_in[0];  // [128,196,2048]
    const float* dh  = (const float*)d_in[1];  // [128,1024]
    const float* Wq  = (const float*)d_in[2];  // [1024,2048]  (A,E)
    const float* bq  = (const float*)d_in[3];  // [1024]
    const float* Wv  = (const float*)d_in[4];  // [1024,2048]  (A,E)
    const float* bv  = (const float*)d_in[5];  // [1024]
    const float* Wd  = (const float*)d_in[6];  // [1024,1024]  (A,D)
    const float* bd  = (const float*)d_in[7];  // [1024]
    float* out = (float*)d_out;                // [128,1024]

    const int gsm = (int)sizeof(SmemGemm);                  // ~57KB dynamic
    const int fsm = (EE + 4 * PDEPTH * EE) * 4;             // 8 + 96 = 104KB
    cudaFuncSetAttribute(gemm_tc<false, 0>, cudaFuncAttributeMaxDynamicSharedMemorySize, gsm);
    cudaFuncSetAttribute(gemm_tc<true, 1>,  cudaFuncAttributeMaxDynamicSharedMemorySize, gsm);
    cudaFuncSetAttribute(gemm_tc<false, 2>, cudaFuncAttributeMaxDynamicSharedMemorySize, gsm);
    cudaFuncSetAttribute(fused_attn_kernel, cudaFuncAttributeMaxDynamicSharedMemorySize, fsm);

    // 1) dec_q = h @ Wd^T + bd   (NT, K=D=1024, split 16 -> 16x16 = 256 CTAs)
    gemm_tc<false, 0><<<dim3(AA / 64, 16), 256, gsm>>>(dh, Wd, DD, AA, DD / 16);
    reduce_add_kernel<1, false, 16><<<(BB * AA) / 1024, 256>>>(nullptr, bd, BB * AA, AA);

    // 2) u partials = dec_q @ Wq (NN, K=A=1024, split USPLIT -> 32x4 = 128 CTAs)
    gemm_tc<true, 1><<<dim3(EE / 64, USPLIT), 256, gsm>>>(nullptr, Wq, AA, EE, AA / USPLIT);

    // 3) fused: u-reduce + c + energies + weights + weighted encoder sum
    fused_attn_kernel<<<dim3(BB, 2), 256, fsm>>>(enc, bq);

    // 4) context = (P0+P1) @ Wv^T, then *1/sum(w) + bv in reduce epilogue
    //    (NT, K=E=2048, split 16 -> 16x16 = 256 CTAs)
    gemm_tc<false, 2><<<dim3(AA / 64, 16), 256, gsm>>>(nullptr, Wv, EE, AA, EE / 16);
    reduce_add_kernel<0, true, 16><<<(BB * AA) / 1024, 256>>>(out, bv, BB * AA, AA);
}

// round 11
// speedup vs baseline: 1.2559x; 1.0284x over previous
#include <cuda_runtime.h>
#include <cstdint>

// Problem constants
#define BB   128   // batch
#define LL   196   // encoder length
#define EE   2048  // encoder dim
#define DD   1024  // decoder dim
#define AA   1024  // attention dim
#define USPLIT 4   // split-K of the u GEMM
#define PDEPTH 3   // per-pair pipeline depth (row slots) in fused kernel

// ---------------- device scratch (no allocations allowed) ----------------
__device__ float g_decq[BB * AA];        // Wd @ h + bd           [128,1024]
__device__ float g_u[BB * EE];           // dec_q @ Wq            [128,2048]
__device__ float g_fpart[2 * BB * EE];   // fused partial sums (unnormalized)
__device__ float g_fden[2 * BB];         // fused partial denominators

// ---------------- helpers ----------------
__device__ __forceinline__ void redadd(float* p, float v) {
    asm volatile("red.global.add.f32 [%0], %1;" :: "l"(p), "f"(v) : "memory");
}

__device__ __forceinline__ void pack2_bf(float x0, float x1,
                                         uint32_t& wh, uint32_t& wl) {
    asm("cvt.rn.bf16x2.f32 %0, %1, %2;" : "=r"(wh) : "f"(x1), "f"(x0));
    float h0 = __uint_as_float(wh << 16);
    float h1 = __uint_as_float(wh & 0xffff0000u);
    float l0 = x0 - h0;
    float l1 = x1 - h1;
    asm("cvt.rn.bf16x2.f32 %0, %1, %2;" : "=r"(wl) : "f"(l1), "f"(l0));
}

__device__ __forceinline__ void mma_bf16(float* c, const uint32_t* a,
                                         uint32_t b0, uint32_t b1) {
    asm volatile(
        "mma.sync.aligned.m16n8k16.row.col.f32.bf16.bf16.f32 "
        "{%0,%1,%2,%3}, {%4,%5,%6,%7}, {%8,%9}, {%0,%1,%2,%3};"
        : "+f"(c[0]), "+f"(c[1]), "+f"(c[2]), "+f"(c[3])
        : "r"(a[0]), "r"(a[1]), "r"(a[2]), "r"(a[3]), "r"(b0), "r"(b1));
}

// Smem: A planes [row][kpair] stride 20 (conflict-free frag reads),
// B packed fragment-major.
struct SmemGemm {
    uint32_t Ah[2][128][20];
    uint32_t Al[2][128][20];
    uint32_t Bp[2][16 * 132];
};

// =====================================================================
// Init: out = bv (broadcast), g_decq = bd (broadcast), g_u = 0.
// grid 512 x 256, one float4 per thread.
// =====================================================================
__global__ void init_kernel(float* __restrict__ out,
                            const float* __restrict__ bv,
                            const float* __restrict__ bd) {
    const int idx = blockIdx.x * blockDim.x + threadIdx.x;   // float4 id
    if (idx < 32768) {                   // out  [128,1024]
        const int f = idx * 4;
        *reinterpret_cast<float4*>(out + f) =
            *reinterpret_cast<const float4*>(bv + (f & (AA - 1)));
    } else if (idx < 65536) {            // g_decq [128,1024]
        const int f = (idx - 32768) * 4;
        *reinterpret_cast<float4*>(g_decq + f) =
            *reinterpret_cast<const float4*>(bd + (f & (AA - 1)));
    } else {                             // g_u [128,2048]
        const int f = (idx - 65536) * 4;
        *reinterpret_cast<float4*>(g_u + f) = make_float4(0.f, 0.f, 0.f, 0.f);
    }
}

// =====================================================================
// Tensor-core bf16x3 GEMM with ATOMIC split-K epilogue:
//   dest[m][n] += sum_{k in chunk s} X[m,k] * W(k,n)   (red.global.add)
//   NN=true : W is [K,N] row-major;  NN=false: W is [N,K] row-major
// XSEL: 0 -> X param, 1 -> g_decq, 2 -> (g_fpart[0]+g_fpart[1]) * inv_row
// OUTSEL: 0 -> outp param, 1 -> g_decq, 2 -> g_u
// =====================================================================
template <bool NN, int XSEL, int OUTSEL>
__global__ void __launch_bounds__(256, 2)
gemm_tc(const float* __restrict__ Xp, const float* __restrict__ W,
        float* __restrict__ outp, int K, int N, int kchunk) {
    extern __shared__ SmemGemm sm_g[];
    SmemGemm* s = sm_g;

    const float* X = (XSEL == 1) ? (const float*)g_decq : Xp;

    const int t     = threadIdx.x;
    const int warp  = t >> 5;
    const int lane  = t & 31;
    const int group = lane >> 2;
    const int tg    = lane & 3;
    const int wm    = warp & 3;
    const int wn    = warp >> 2;
    const int n0    = blockIdx.x * 64;
    const int k0    = blockIdx.y * kchunk;

    float c[2][4][4];
#pragma unroll
    for (int mi = 0; mi < 2; mi++)
#pragma unroll
        for (int ni = 0; ni < 4; ni++)
#pragma unroll
            for (int r = 0; r < 4; r++) c[mi][ni][r] = 0.f;

    // per-row 1/sum(w) factors for the context GEMM (XSEL==2)
    float invj[4];
    if (XSEL == 2) {
#pragma unroll
        for (int j = 0; j < 4; j++) {
            const int row = (t + 256 * j) >> 3;
            invj[j] = 1.f / (g_fden[row] + g_fden[BB + row]);
        }
    }

    float4 ra[4];
    float4 rb[2];

    auto loadA = [&](int kt) {
#pragma unroll
        for (int j = 0; j < 4; j++) {
            const int idx = t + 256 * j;
            const int row = idx >> 3;
            const int kq  = idx & 7;
            if (XSEL == 2) {
                float4 p0 = *reinterpret_cast<const float4*>(
                    g_fpart + (size_t)row * EE + kt + kq * 4);
                float4 p1 = *reinterpret_cast<const float4*>(
                    g_fpart + (size_t)(BB + row) * EE + kt + kq * 4);
                const float iv = invj[j];
                ra[j] = make_float4((p0.x + p1.x) * iv, (p0.y + p1.y) * iv,
                                    (p0.z + p1.z) * iv, (p0.w + p1.w) * iv);
            } else {
                ra[j] = *reinterpret_cast<const float4*>(X + (size_t)row * K + kt + kq * 4);
            }
        }
    };
    auto loadB = [&](int kt) {
        if (NN) {
            const int kp = t >> 4;
            const int nq = t & 15;
            rb[0] = *reinterpret_cast<const float4*>(W + (size_t)(kt + 2 * kp) * N + n0 + nq * 4);
            rb[1] = *reinterpret_cast<const float4*>(W + (size_t)(kt + 2 * kp + 1) * N + n0 + nq * 4);
        } else {
#pragma unroll
            for (int j = 0; j < 2; j++) {
                const int idx = t + 256 * j;
                const int n   = idx >> 3;
                const int kq  = idx & 7;
                rb[j] = *reinterpret_cast<const float4*>(W + (size_t)(n0 + n) * K + kt + kq * 4);
            }
        }
    };
    auto storeAB = [&](int bb) {
#pragma unroll
        for (int j = 0; j < 4; j++) {
            const int idx = t + 256 * j;
            const int row = idx >> 3;
            const int kq  = idx & 7;
            uint32_t wh0, wl0, wh1, wl1;
            pack2_bf(ra[j].x, ra[j].y, wh0, wl0);
            pack2_bf(ra[j].z, ra[j].w, wh1, wl1);
            *reinterpret_cast<uint2*>(&s->Ah[bb][row][2 * kq]) = make_uint2(wh0, wh1);
            *reinterpret_cast<uint2*>(&s->Al[bb][row][2 * kq]) = make_uint2(wl0, wl1);
        }
        uint32_t* bp = s->Bp[bb];
        if (NN) {
            const int kp   = t >> 4;
            const int nq   = t & 15;
            const int ks16 = kp >> 3;
            const int pp   = kp & 7;
            const int breg = (pp >= 4) ? 1 : 0;
            const int tgk  = pp & 3;
            const float e0[4] = {rb[0].x, rb[0].y, rb[0].z, rb[0].w};
            const float e1[4] = {rb[1].x, rb[1].y, rb[1].z, rb[1].w};
#pragma unroll
            for (int cc = 0; cc < 4; cc++) {
                const int n  = nq * 4 + cc;
                const int bi = (n >> 3) * 2 + ks16;
                uint32_t wh, wl;
                pack2_bf(e0[cc], e1[cc], wh, wl);
                uint32_t* base = bp + bi * 132 + ((n & 7) * 4 + tgk) * 4;
                base[breg]     = wh;
                base[breg + 2] = wl;
            }
        } else {
#pragma unroll
            for (int j = 0; j < 2; j++) {
                const int idx  = t + 256 * j;
                const int n    = idx >> 3;
                const int kq   = idx & 7;
                const int ks16 = kq >> 2;
                const int bi   = (n >> 3) * 2 + ks16;
                uint32_t* tb = bp + bi * 132 + ((n & 7) * 4) * 4;
                const float vals[4] = {rb[j].x, rb[j].y, rb[j].z, rb[j].w};
#pragma unroll
                for (int q = 0; q < 2; q++) {
                    const int pp   = (2 * kq + q) & 7;
                    const int breg = (pp >= 4) ? 1 : 0;
                    const int tgk  = pp & 3;
                    uint32_t wh, wl;
                    pack2_bf(vals[2 * q], vals[2 * q + 1], wh, wl);
                    uint32_t* base = tb + tgk * 4;
                    base[breg]     = wh;
                    base[breg + 2] = wl;
                }
            }
        }
    };
    auto compute = [&](int bb) {
        const uint32_t* bp = s->Bp[bb];
#pragma unroll
        for (int ks = 0; ks < 2; ks++) {
            const int base = ks * 8;
            uint32_t ah[2][4], al[2][4];
#pragma unroll
            for (int mi = 0; mi < 2; mi++) {
                const int rm = wm * 32 + mi * 16 + group;
                ah[mi][0] = s->Ah[bb][rm][base + tg];
                ah[mi][1] = s->Ah[bb][rm + 8][base + tg];
                ah[mi][2] = s->Ah[bb][rm][base + tg + 4];
                ah[mi][3] = s->Ah[bb][rm + 8][base + tg + 4];
                al[mi][0] = s->Al[bb][rm][base + tg];
                al[mi][1] = s->Al[bb][rm + 8][base + tg];
                al[mi][2] = s->Al[bb][rm][base + tg + 4];
                al[mi][3] = s->Al[bb][rm + 8][base + tg + 4];
            }
#pragma unroll
            for (int ni = 0; ni < 4; ni++) {
                const uint32_t* Bf = bp + ((wn * 4 + ni) * 2 + ks) * 132 + lane * 4;
                uint4 bv = *reinterpret_cast<const uint4*>(Bf);
#pragma unroll
                for (int mi = 0; mi < 2; mi++) {
                    mma_bf16(c[mi][ni], ah[mi], bv.x, bv.y);
                    mma_bf16(c[mi][ni], ah[mi], bv.z, bv.w);
                    mma_bf16(c[mi][ni], al[mi], bv.x, bv.y);
                }
            }
        }
    };

    loadA(k0);
    loadB(k0);
    storeAB(0);
    __syncthreads();

    const int nkb = kchunk >> 5;
    for (int kb = 0; kb < nkb; kb++) {
        const int cur = kb & 1;
        if (kb + 1 < nkb) {
            loadA(k0 + (kb + 1) * 32);
            loadB(k0 + (kb + 1) * 32);
        }
        compute(cur);
        if (kb + 1 < nkb) storeAB(cur ^ 1);
        __syncthreads();
    }

    // ---- atomic epilogue straight into the destination
    float* ob = (OUTSEL == 0) ? outp : (OUTSEL == 1 ? (float*)g_decq : (float*)g_u);
#pragma unroll
    for (int mi = 0; mi < 2; mi++) {
        const int row0 = wm * 32 + mi * 16 + group;
#pragma unroll
        for (int ni = 0; ni < 4; ni++) {
            const int col = n0 + wn * 32 + ni * 8 + 2 * tg;
            redadd(ob + (size_t)row0 * N + col,           c[mi][ni][0]);
            redadd(ob + (size_t)row0 * N + col + 1,       c[mi][ni][1]);
            redadd(ob + (size_t)(row0 + 8) * N + col,     c[mi][ni][2]);
            redadd(ob + (size_t)(row0 + 8) * N + col + 1, c[mi][ni][3]);
        }
    }
}

// =====================================================================
// Fused attention pass, per-pair decoupled cp.async pipelines.
// grid (BB, 2), 256 threads = 8 warps = 4 warp PAIRS.
// (unchanged from R10 except u is read directly from g_u)
// =====================================================================
__global__ void __launch_bounds__(256, 2)
fused_attn_kernel(const float* __restrict__ enc, const float* __restrict__ bq) {
    const int b    = blockIdx.x;
    const int sp   = blockIdx.y;       // 0..1
    const int t    = threadIdx.x;      // 256
    const int warp = t >> 5;
    const int lane = t & 31;
    const int pair = warp >> 1;        // 0..3
    const int half = warp & 1;         // 0/1 : which half of the row
    const int lstart = sp * 98;
    const int nrows  = (98 - pair + 3) >> 2;   // pairs 0,1: 25; pairs 2,3: 24

    extern __shared__ float smf[];
    float* u_s = smf;                            // [2048]  (8KB)
    float* buf = smf + EE;                       // [4][PDEPTH][2048] (96KB)
    __shared__ float cred[8];
    __shared__ float dpair[4];
    __shared__ float pd[4][2][2];                // [pair][parity][half]
    __shared__ float c_sh;

    // ---- stage u[b] (complete sum, atomics done by previous launch)
#pragma unroll
    for (int j = 0; j < 2; j++) {
        const int p = t + 256 * j;               // float4 index 0..511
        *reinterpret_cast<float4*>(u_s + 4 * p) =
            *reinterpret_cast<const float4*>(g_u + (size_t)b * EE + 4 * p);
    }

    // ---- c[b] = bq . dec_q[b] (fixed order)
    {
        const float* dq = g_decq + (size_t)b * AA;
        float cv = bq[t] * dq[t] + bq[t + 256] * dq[t + 256]
                 + bq[t + 512] * dq[t + 512] + bq[t + 768] * dq[t + 768];
#pragma unroll
        for (int o = 16; o > 0; o >>= 1) cv += __shfl_xor_sync(0xffffffffu, cv, o);
        if (lane == 0) cred[warp] = cv;
    }
    __syncthreads();
    if (t == 0) {
        float tot = 0.f;
        for (int i = 0; i < 8; i++) tot += cred[i];
        c_sh = tot;
    }
    __syncthreads();
    const float c_b = c_sh;

    const float* encb = enc + (size_t)b * LL * EE;
    float* mybuf = buf + (size_t)(pair * PDEPTH) * EE;     // this pair's slots
    const int fo = half * 256 + lane;                       // float4 offset base

    auto fill = [&](int i) {
        if (i < nrows) {
            const int l = lstart + pair + 4 * i;
            const float4* src = reinterpret_cast<const float4*>(encb + (size_t)l * EE) + fo;
            uint32_t sa = (uint32_t)__cvta_generic_to_shared(mybuf + (size_t)(i % PDEPTH) * EE)
                        + (uint32_t)fo * 16u;
#pragma unroll
            for (int q = 0; q < 8; q++) {
                asm volatile("cp.async.cg.shared.global [%0], [%1], 16;\n"
                             :: "r"(sa + q * 512u), "l"(src + q * 32));
            }
        }
        asm volatile("cp.async.commit_group;\n");
    };

    float4 ma[8];
#pragma unroll
    for (int i = 0; i < 8; i++) ma[i] = make_float4(0.f, 0.f, 0.f, 0.f);
    float den = 0.f;

    const float4* us4 = reinterpret_cast<const float4*>(u_s) + half * 256;
    const int barid = pair + 1;                   // named barriers 1..4, 64 thr

    fill(0); fill(1); fill(2);

    for (int i = 0; i < nrows; i++) {
        asm volatile("cp.async.wait_group %0;\n" :: "n"(PDEPTH - 1) : "memory");
        const float4* slot = reinterpret_cast<const float4*>(
            mybuf + (size_t)(i % PDEPTH) * EE) + fo;
        float4 x[8];
#pragma unroll
        for (int q = 0; q < 8; q++) x[q] = slot[q * 32];
        float d = 0.f;
#pragma unroll
        for (int q = 0; q < 8; q++) {
            float4 uu = us4[lane + 32 * q];
            d += x[q].x * uu.x + x[q].y * uu.y + x[q].z * uu.z + x[q].w * uu.w;
        }
#pragma unroll
        for (int o = 16; o > 0; o >>= 1) d += __shfl_xor_sync(0xffffffffu, d, o);
        const int par = i & 1;
        if (lane == 0) pd[pair][par][half] = d;
        asm volatile("bar.sync %0, 64;" :: "r"(barid) : "memory");
        const float z  = pd[pair][par][0] + pd[pair][par][1] + c_b;
        const float th = 1.f - __fdividef(2.f, __expf(2.f * z) + 1.f);
        const float w  = __expf(th);
        if (half == 0) den += w;
#pragma unroll
        for (int q = 0; q < 8; q++) {
            ma[q].x += w * x[q].x; ma[q].y += w * x[q].y;
            ma[q].z += w * x[q].z; ma[q].w += w * x[q].w;
        }
        fill(i + PDEPTH);
    }

    asm volatile("cp.async.wait_group 0;\n" ::: "memory");
    __syncthreads();

    float* sacc = buf;                            // [4][2048]
    float4* sw = reinterpret_cast<float4*>(sacc + (size_t)pair * EE) + fo;
#pragma unroll
    for (int q = 0; q < 8; q++) sw[q * 32] = ma[q];
    if (half == 0 && lane == 0) dpair[pair] = den;
    __syncthreads();

    float* pp = g_fpart + ((size_t)sp * BB + b) * EE;
#pragma unroll
    for (int j = 0; j < 2; j++) {
        const int p = t + 256 * j;                // float4 index 0..511
        float4 a = reinterpret_cast<const float4*>(sacc)[p];
#pragma unroll
        for (int q = 1; q < 4; q++) {
            float4 v = reinterpret_cast<const float4*>(sacc + (size_t)q * EE)[p];
            a.x += v.x; a.y += v.y; a.z += v.z; a.w += v.w;
        }
        reinterpret_cast<float4*>(pp)[p] = a;
    }
    if (t == 0) g_fden[sp * BB + b] = dpair[0] + dpair[1] + dpair[2] + dpair[3];
}

// =====================================================================
// Launcher
// =====================================================================
extern "C" void kernel_launch(void* const* d_in, const int* in_sizes, int n_in,
                              void* d_out, int out_size) {
    const float* enc = (const float*)d_in[0];  // [128,196,2048]
    const float* dh  = (const float*)d_in[1];  // [128,1024]
    const float* Wq  = (const float*)d_in[2];  // [1024,2048]  (A,E)
    const float* bq  = (const float*)d_in[3];  // [1024]
    const float* Wv  = (const float*)d_in[4];  // [1024,2048]  (A,E)
    const float* bv  = (const float*)d_in[5];  // [1024]
    const float* Wd  = (const float*)d_in[6];  // [1024,1024]  (A,D)
    const float* bd  = (const float*)d_in[7];  // [1024]
    float* out = (float*)d_out;                // [128,1024]

    const int gsm = (int)sizeof(SmemGemm);                  // ~57KB dynamic
    const int fsm = (EE + 4 * PDEPTH * EE) * 4;             // 8 + 96 = 104KB
    cudaFuncSetAttribute(gemm_tc<false, 0, 1>, cudaFuncAttributeMaxDynamicSharedMemorySize, gsm);
    cudaFuncSetAttribute(gemm_tc<true, 1, 2>,  cudaFuncAttributeMaxDynamicSharedMemorySize, gsm);
    cudaFuncSetAttribute(gemm_tc<false, 2, 0>, cudaFuncAttributeMaxDynamicSharedMemorySize, gsm);
    cudaFuncSetAttribute(fused_attn_kernel,    cudaFuncAttributeMaxDynamicSharedMemorySize, fsm);

    // 0) init destinations with biases / zero
    init_kernel<<<512, 256>>>(out, bv, bd);

    // 1) g_decq += h @ Wd^T       (NT, K=D=1024, split 16 -> 256 CTAs)
    gemm_tc<false, 0, 1><<<dim3(AA / 64, 16), 256, gsm>>>(dh, Wd, nullptr, DD, AA, DD / 16);

    // 2) g_u += dec_q @ Wq        (NN, K=A=1024, split 4 -> 128 CTAs)
    gemm_tc<true, 1, 2><<<dim3(EE / 64, USPLIT), 256, gsm>>>(nullptr, Wq, nullptr, AA, EE, AA / USPLIT);

    // 3) fused: c + energies + weights + weighted encoder sum
    fused_attn_kernel<<<dim3(BB, 2), 256, fsm>>>(enc, bq);

    // 4) out += ((P0+P1)*inv) @ Wv^T   (NT, K=E=2048, split 16 -> 256 CTAs)
    gemm_tc<false, 2, 0><<<dim3(AA / 64, 16), 256, gsm>>>(nullptr, Wv, out, EE, AA, EE / 16);
}